// round 5
// baseline (speedup 1.0000x reference)
#include <cuda_runtime.h>

#define NN 20000
#define NE 400000
#define NB 4
#define HID 256
#define OD 128

__device__ __align__(16) float g_YZ[NN * 512];
__device__ float g_S[NB * HID];
__device__ int g_is_i64;

typedef unsigned long long u64;
typedef unsigned int u32;

__device__ __forceinline__ u64 pk2(float lo, float hi) {
    u64 r;
    asm("mov.b64 %0, {%1, %2};" : "=l"(r) : "r"(__float_as_uint(lo)), "r"(__float_as_uint(hi)));
    return r;
}
__device__ __forceinline__ void upk2(u64 p, float &lo, float &hi) {
    unsigned a, b;
    asm("mov.b64 {%0, %1}, %2;" : "=r"(a), "=r"(b) : "l"(p));
    lo = __uint_as_float(a); hi = __uint_as_float(b);
}
__device__ __forceinline__ void upk2u(u64 p, u32 &lo, u32 &hi) {
    asm("mov.b64 {%0, %1}, %2;" : "=r"(lo), "=r"(hi) : "l"(p));
}
__device__ __forceinline__ u64 add2(u64 a, u64 b) {
    u64 d;
    asm("add.rn.f32x2 %0, %1, %2;" : "=l"(d) : "l"(a), "l"(b));
    return d;
}
__device__ __forceinline__ u32 cvt_tf32(float f) {
    u32 r;
    asm("cvt.rna.tf32.f32 %0, %1;" : "=r"(r) : "f"(f));
    return r;
}
__device__ __forceinline__ void mma_tf32(float &d0, float &d1, float &d2, float &d3,
                                         u32 a0, u32 a1, u32 a2, u32 a3,
                                         u32 b0, u32 b1,
                                         float c0, float c1, float c2, float c3) {
    asm volatile("mma.sync.aligned.m16n8k8.row.col.f32.tf32.tf32.f32 "
                 "{%0,%1,%2,%3}, {%4,%5,%6,%7}, {%8,%9}, {%10,%11,%12,%13};"
                 : "=f"(d0), "=f"(d1), "=f"(d2), "=f"(d3)
                 : "r"(a0), "r"(a1), "r"(a2), "r"(a3), "r"(b0), "r"(b1),
                   "f"(c0), "f"(c1), "f"(c2), "f"(c3));
}

// ---------------------------------------------------------------------------
// Kernel 0: dtype probe (int32 vs int64 edge_index).
// ---------------------------------------------------------------------------
__global__ void detect_dtype(const void* __restrict__ eraw) {
    const long long* p = (const long long*)eraw;
    int lane = threadIdx.x;
    long long v0 = p[lane];
    long long v1 = p[64 + lane];
    bool ok = (v0 >= 0 && v0 < NN) && (v1 >= 0 && v1 < NN);
    unsigned m = __ballot_sync(0xffffffffu, ok);
    if (lane == 0) g_is_i64 = (m == 0xffffffffu) ? 1 : 0;
}

// ---------------------------------------------------------------------------
// Kernel 1 (v2): YZ = x @ [W_src | W_dst] on tf32 mma.sync.
// BM=64, BN=128, BK=16. 8 warps, warp tile 32x32 (2 mtiles x 4 ntiles).
// smem rows padded to 24 words -> conflict-free LDS.64 for both A and B frags.
// k stored pair-permuted: word(k) = (k&8) + 2*(k&3) + ((k&4)?1:0) so that the
// (k=t, k=t+4) fragment pair is one aligned LDS.64.
// ---------------------------------------------------------------------------
__global__ __launch_bounds__(256) void node_gemm(const float* __restrict__ x,
                                                 const float* __restrict__ We) {
    __shared__ u32 As[64][24];
    __shared__ u32 Bs[128][24];

    const int m0 = blockIdx.y * 64;
    const int n0 = blockIdx.x * 128;
    const int rb = (n0 >= 256) ? 256 : 0; // W_edge row base (W_src vs W_dst)
    const int cb = n0 - rb;               // W_edge col base (0 or 128)
    const int tid = threadIdx.x;
    const int warp = tid >> 5, lane = tid & 31, g = lane >> 2, t = lane & 3;
    const int wm = warp >> 2, wn = warp & 3;

    float acc[2][4][4] = {};

    for (int k0 = 0; k0 < 256; k0 += 16) {
        __syncthreads();
        // ---- stage A: 64 rows x 16 k (tf32, k pair-permuted) ----
        {
            int r = tid >> 2, kk4 = (tid & 3) * 4;
            int m = m0 + r;
            float4 v = make_float4(0.f, 0.f, 0.f, 0.f);
            if (m < NN) v = *(const float4*)(x + (size_t)m * 256 + k0 + kk4);
            int bw = (kk4 & 8) + ((kk4 & 4) ? 1 : 0);
            u32* dst = &As[r][bw];
            dst[0] = cvt_tf32(v.x); dst[2] = cvt_tf32(v.y);
            dst[4] = cvt_tf32(v.z); dst[6] = cvt_tf32(v.w);
        }
        // ---- stage B: 16 k x 128 n, stored transposed [n][k-perm] ----
        {
            int n4 = (tid & 31) * 4, kk = tid >> 5;
            #pragma unroll
            for (int rep = 0; rep < 2; rep++) {
                int k = kk + 8 * rep;
                float4 v = *(const float4*)(We + (size_t)(rb + k0 + k) * 256 + cb + n4);
                int w = (k & 8) + 2 * (k & 3) + ((k & 4) ? 1 : 0);
                Bs[n4 + 0][w] = cvt_tf32(v.x);
                Bs[n4 + 1][w] = cvt_tf32(v.y);
                Bs[n4 + 2][w] = cvt_tf32(v.z);
                Bs[n4 + 3][w] = cvt_tf32(v.w);
            }
        }
        __syncthreads();

        u32 a[2][2][4];
        #pragma unroll
        for (int mt = 0; mt < 2; mt++) {
            const u64* rL = (const u64*)As[wm * 32 + mt * 16 + g];
            const u64* rH = (const u64*)As[wm * 32 + mt * 16 + g + 8];
            #pragma unroll
            for (int j = 0; j < 2; j++) {
                u64 pl = rL[j * 4 + t], ph = rH[j * 4 + t];
                upk2u(pl, a[mt][j][0], a[mt][j][2]);
                upk2u(ph, a[mt][j][1], a[mt][j][3]);
            }
        }
        u32 bf[4][2][2];
        #pragma unroll
        for (int nt = 0; nt < 4; nt++) {
            const u64* rn = (const u64*)Bs[wn * 32 + nt * 8 + g];
            #pragma unroll
            for (int j = 0; j < 2; j++) {
                u64 p = rn[j * 4 + t];
                upk2u(p, bf[nt][j][0], bf[nt][j][1]);
            }
        }
        #pragma unroll
        for (int mt = 0; mt < 2; mt++)
            #pragma unroll
            for (int nt = 0; nt < 4; nt++)
                #pragma unroll
                for (int j = 0; j < 2; j++)
                    mma_tf32(acc[mt][nt][0], acc[mt][nt][1], acc[mt][nt][2], acc[mt][nt][3],
                             a[mt][j][0], a[mt][j][1], a[mt][j][2], a[mt][j][3],
                             bf[nt][j][0], bf[nt][j][1],
                             acc[mt][nt][0], acc[mt][nt][1], acc[mt][nt][2], acc[mt][nt][3]);
    }

    #pragma unroll
    for (int mt = 0; mt < 2; mt++) {
        int mrow = m0 + wm * 32 + mt * 16 + g;
        #pragma unroll
        for (int nt = 0; nt < 4; nt++) {
            int col = n0 + wn * 32 + nt * 8 + 2 * t;
            if (mrow < NN)
                *(float2*)(g_YZ + (size_t)mrow * 512 + col) = make_float2(acc[mt][nt][0], acc[mt][nt][1]);
            if (mrow + 8 < NN)
                *(float2*)(g_YZ + (size_t)(mrow + 8) * 512 + col) = make_float2(acc[mt][nt][2], acc[mt][nt][3]);
        }
    }
}

__global__ void zero_s() { g_S[threadIdx.x] = 0.f; }

// ---------------------------------------------------------------------------
// Kernel 3 (v4): edge stage, tensor-core mma with PERMUTED column mapping:
//   phys col(nt, n) = hbase + 8*(n>>1) + 2*nt + (n&1)
// so each thread's 8 base columns are CONTIGUOUS (32B) -> gathers are LDG.128
// (8 per warp-sub instead of 16 LDG.64), no shuffles. attr smem is k-pair
// permuted + stride-24 padded -> conflict-free LDS.64 A-frags.
// ---------------------------------------------------------------------------
__global__ __launch_bounds__(256, 2) void edge_kernel(const void* __restrict__ eraw,
                                                      const float* __restrict__ attrs,
                                                      const float* __restrict__ We,
                                                      const float* __restrict__ b_edge) {
    __shared__ u32 attr_s[NB][32][24];   // [b][edge][k-perm], stride 24 words
    __shared__ int sidx_s[32], didx_s[32];
    __shared__ float Ssh[NB * HID];

    const int tid = threadIdx.x;
    for (int i = tid; i < NB * HID; i += 256) Ssh[i] = 0.f;

    const int warp = tid >> 5;
    const int lane = tid & 31;
    const int g = lane >> 2;
    const int t = lane & 3;
    const int hbase = warp * 32;

    // Persistent B-frags under permuted mapping: frag n = g -> col hbase + 8*(g>>1) + 2nt + (g&1)
    u32 Bf[4][2][2];
    const int colB = hbase + 8 * (g >> 1) + (g & 1);
    #pragma unroll
    for (int nt = 0; nt < 4; nt++)
        #pragma unroll
        for (int ks = 0; ks < 2; ks++) {
            Bf[nt][ks][0] = cvt_tf32(We[(512 + t + 8 * ks) * 256 + colB + 2 * nt]);
            Bf[nt][ks][1] = cvt_tf32(We[(512 + t + 4 + 8 * ks) * 256 + colB + 2 * nt]);
        }
    // bias: thread t's 8 contiguous cols [hbase+8t, +8)
    u64 bias4[4];
    {
        const u64* bp = (const u64*)(b_edge + hbase + 8 * t);
        bias4[0] = bp[0]; bias4[1] = bp[1]; bias4[2] = bp[2]; bias4[3] = bp[3];
    }

    const int is64 = g_is_i64;
    const long long* e64 = (const long long*)eraw;
    const int*       e32 = (const int*)eraw;

    u64 acc[NB][4] = {};

    const int nchunks = NE / 32;
    for (int c = blockIdx.x; c < nchunks; c += gridDim.x) {
        const int e0 = c * 32;
        __syncthreads();
        // ---- stage indices + attrs (tf32, k pair-permuted) ----
        if (tid < 32)      sidx_s[tid]      = is64 ? (int)e64[e0 + tid]           : e32[e0 + tid];
        else if (tid < 64) didx_s[tid - 32] = is64 ? (int)e64[NE + e0 + tid - 32] : e32[NE + e0 + tid - 32];
        {
            int b = tid >> 6, r = tid & 63;
            const float4* src = (const float4*)(attrs + ((size_t)b * NE + e0) * 16);
            #pragma unroll
            for (int k2 = 0; k2 < 2; k2++) {
                float4 v = src[r * 2 + k2];
                int flat = (r * 2 + k2) * 4;
                int e = flat >> 4, a0i = flat & 15;
                int bw = (a0i & 8) + ((a0i & 4) ? 1 : 0);
                u32* dst = &attr_s[b][e][bw];
                dst[0] = cvt_tf32(v.x); dst[2] = cvt_tf32(v.y);
                dst[4] = cvt_tf32(v.z); dst[6] = cvt_tf32(v.w);
            }
        }
        __syncthreads();

        #pragma unroll
        for (int sub = 0; sub < 2; sub++) {
            const int eb = sub * 16;
            const int sl = sidx_s[eb + g],     dl = didx_s[eb + g];
            const int sh = sidx_s[eb + g + 8], dh = didx_s[eb + g + 8];

            // contiguous 32B gathers per row (2 x LDG.128 each)
            const ulonglong2* pyl = (const ulonglong2*)(g_YZ + (size_t)sl * 512 + hbase + 8 * t);
            const ulonglong2* pyh = (const ulonglong2*)(g_YZ + (size_t)sh * 512 + hbase + 8 * t);
            const ulonglong2* pzl = (const ulonglong2*)(g_YZ + (size_t)dl * 512 + 256 + hbase + 8 * t);
            const ulonglong2* pzh = (const ulonglong2*)(g_YZ + (size_t)dh * 512 + 256 + hbase + 8 * t);
            ulonglong2 yl0 = pyl[0], yl1 = pyl[1];
            ulonglong2 yh0 = pyh[0], yh1 = pyh[1];
            ulonglong2 zl0 = pzl[0], zl1 = pzl[1];
            ulonglong2 zh0 = pzh[0], zh1 = pzh[1];

            u64 bLo[4], bHi[4];
            bLo[0] = add2(add2(yl0.x, zl0.x), bias4[0]);
            bLo[1] = add2(add2(yl0.y, zl0.y), bias4[1]);
            bLo[2] = add2(add2(yl1.x, zl1.x), bias4[2]);
            bLo[3] = add2(add2(yl1.y, zl1.y), bias4[3]);
            bHi[0] = add2(add2(yh0.x, zh0.x), bias4[0]);
            bHi[1] = add2(add2(yh0.y, zh0.y), bias4[1]);
            bHi[2] = add2(add2(yh1.x, zh1.x), bias4[2]);
            bHi[3] = add2(add2(yh1.y, zh1.y), bias4[3]);

            #pragma unroll
            for (int b = 0; b < NB; b++) {
                const u64* arL = (const u64*)attr_s[b][eb + g];
                const u64* arH = (const u64*)attr_s[b][eb + g + 8];
                u32 a0, a1, a2, a3, a4, a5, a6, a7;
                upk2u(arL[t],     a0, a2);
                upk2u(arH[t],     a1, a3);
                upk2u(arL[t + 4], a4, a6);
                upk2u(arH[t + 4], a5, a7);
                #pragma unroll
                for (int nt = 0; nt < 4; nt++) {
                    float c0, c1, c2, c3;
                    upk2(bLo[nt], c0, c1);
                    upk2(bHi[nt], c2, c3);
                    float d0, d1, d2, d3;
                    mma_tf32(d0, d1, d2, d3, a0, a1, a2, a3, Bf[nt][0][0], Bf[nt][0][1], c0, c1, c2, c3);
                    mma_tf32(d0, d1, d2, d3, a4, a5, a6, a7, Bf[nt][1][0], Bf[nt][1][1], d0, d1, d2, d3);
                    acc[b][nt] = add2(acc[b][nt], pk2(fmaxf(d0, 0.f), fmaxf(d1, 0.f)));
                    acc[b][nt] = add2(acc[b][nt], pk2(fmaxf(d2, 0.f), fmaxf(d3, 0.f)));
                }
            }
        }
    }

    // ---- reduce over g (fixed t), then write under permuted mapping ----
    #pragma unroll
    for (int b = 0; b < NB; b++)
        #pragma unroll
        for (int nt = 0; nt < 4; nt++) {
            u64 v = acc[b][nt];
            v = add2(v, __shfl_down_sync(0xffffffffu, v, 16));
            v = add2(v, __shfl_down_sync(0xffffffffu, v, 8));
            v = add2(v, __shfl_down_sync(0xffffffffu, v, 4));
            acc[b][nt] = v;
        }
    if (lane < 4) {
        #pragma unroll
        for (int b = 0; b < NB; b++)
            #pragma unroll
            for (int nt = 0; nt < 4; nt++) {
                float lo, hi;
                upk2(acc[b][nt], lo, hi);
                int h = hbase + 8 * lane + 2 * nt;
                atomicAdd(&Ssh[b * 256 + h], lo);
                atomicAdd(&Ssh[b * 256 + h + 1], hi);
            }
    }
    __syncthreads();
    for (int i = tid; i < NB * HID; i += 256) atomicAdd(&g_S[i], Ssh[i]);
}

// ---------------------------------------------------------------------------
// Kernel 4: out = (S/NE) @ W_graph + b_graph
// ---------------------------------------------------------------------------
__global__ void final_kernel(const float* __restrict__ Wg,
                             const float* __restrict__ bg,
                             float* __restrict__ out) {
    const int t = threadIdx.x; // 512 threads
    const int b = t >> 7, o = t & 127;
    const float invE = 1.0f / (float)NE;
    float dot = 0.f;
    #pragma unroll 8
    for (int h = 0; h < 256; h++)
        dot += g_S[b * 256 + h] * Wg[h * 128 + o];
    out[t] = fmaf(dot, invE, bg[o]);
}

extern "C" void kernel_launch(void* const* d_in, const int* in_sizes, int n_in,
                              void* d_out, int out_size) {
    const float* x     = (const float*)d_in[0];
    const void*  eidx  = d_in[1];
    const float* attrs = (const float*)d_in[2];
    const float* We    = (const float*)d_in[3];
    const float* be    = (const float*)d_in[4];
    const float* Wg    = (const float*)d_in[5];
    const float* bg    = (const float*)d_in[6];
    float* out = (float*)d_out;

    detect_dtype<<<1, 32>>>(eidx);
    dim3 gn(4, 313);
    node_gemm<<<gn, 256>>>(x, We);
    zero_s<<<1, NB * HID>>>();
    edge_kernel<<<296, 256>>>(eidx, attrs, We, be);
    final_kernel<<<1, 512>>>(Wg, bg, out);
}

// round 6
// speedup vs baseline: 1.5736x; 1.5736x over previous
#include <cuda_runtime.h>

#define NN 20000
#define NE 400000
#define NB 4
#define HID 256
#define OD 128

__device__ __align__(16) float g_YZ[NN * 512];
__device__ float g_S[NB * HID];
__device__ int g_is_i64;

typedef unsigned long long u64;
typedef unsigned int u32;

__device__ __forceinline__ u64 pk2(float lo, float hi) {
    u64 r;
    asm("mov.b64 %0, {%1, %2};" : "=l"(r) : "r"(__float_as_uint(lo)), "r"(__float_as_uint(hi)));
    return r;
}
__device__ __forceinline__ void upk2(u64 p, float &lo, float &hi) {
    unsigned a, b;
    asm("mov.b64 {%0, %1}, %2;" : "=r"(a), "=r"(b) : "l"(p));
    lo = __uint_as_float(a); hi = __uint_as_float(b);
}
__device__ __forceinline__ void upk2u(u64 p, u32 &lo, u32 &hi) {
    asm("mov.b64 {%0, %1}, %2;" : "=r"(lo), "=r"(hi) : "l"(p));
}
__device__ __forceinline__ u64 add2(u64 a, u64 b) {
    u64 d;
    asm("add.rn.f32x2 %0, %1, %2;" : "=l"(d) : "l"(a), "l"(b));
    return d;
}
__device__ __forceinline__ u32 cvt_tf32(float f) {
    u32 r;
    asm("cvt.rna.tf32.f32 %0, %1;" : "=r"(r) : "f"(f));
    return r;
}
__device__ __forceinline__ void mma_tf32(float &d0, float &d1, float &d2, float &d3,
                                         u32 a0, u32 a1, u32 a2, u32 a3,
                                         u32 b0, u32 b1,
                                         float c0, float c1, float c2, float c3) {
    asm volatile("mma.sync.aligned.m16n8k8.row.col.f32.tf32.tf32.f32 "
                 "{%0,%1,%2,%3}, {%4,%5,%6,%7}, {%8,%9}, {%10,%11,%12,%13};"
                 : "=f"(d0), "=f"(d1), "=f"(d2), "=f"(d3)
                 : "r"(a0), "r"(a1), "r"(a2), "r"(a3), "r"(b0), "r"(b1),
                   "f"(c0), "f"(c1), "f"(c2), "f"(c3));
}

// ---------------------------------------------------------------------------
// Kernel 0: dtype probe (int32 vs int64 edge_index).
// ---------------------------------------------------------------------------
__global__ void detect_dtype(const void* __restrict__ eraw) {
    const long long* p = (const long long*)eraw;
    int lane = threadIdx.x;
    long long v0 = p[lane];
    long long v1 = p[64 + lane];
    bool ok = (v0 >= 0 && v0 < NN) && (v1 >= 0 && v1 < NN);
    unsigned m = __ballot_sync(0xffffffffu, ok);
    if (lane == 0) g_is_i64 = (m == 0xffffffffu) ? 1 : 0;
}

// ---------------------------------------------------------------------------
// Kernel 1 (v3): YZ = x @ [W_src | W_dst], tf32 mma, DOUBLE-BUFFERED.
// BM=64, BN=128, BK=16. 8 warps, warp tile 32x32.
// A smem: [2][64][24] k-pair-permuted (LDS.64 frag reads conflict-free).
// B smem: [2][16][136] plain [k][n] (stride 136 -> STS.128 stores AND LDS.32
//         frag reads conflict-free; fixes R5's 32-way STS conflict).
// ---------------------------------------------------------------------------
__global__ __launch_bounds__(256) void node_gemm(const float* __restrict__ x,
                                                 const float* __restrict__ We) {
    __shared__ u32 As[2][64][24];
    __shared__ __align__(16) u32 Bs[2][16][136];

    const int m0 = blockIdx.y * 64;
    const int n0 = blockIdx.x * 128;
    const int rb = (n0 >= 256) ? 256 : 0; // W_edge row base (W_src vs W_dst)
    const int cb = n0 - rb;               // W_edge col base (0 or 128)
    const int tid = threadIdx.x;
    const int warp = tid >> 5, lane = tid & 31, g = lane >> 2, t = lane & 3;
    const int wm = warp >> 2, wn = warp & 3;

    // staging indices
    const int ar = tid >> 2, ak4 = (tid & 3) * 4;          // A: row, k-offset
    const int abw = (ak4 & 8) + ((ak4 & 4) ? 1 : 0);       // A perm word base
    const int bk = tid >> 5, bn4 = (tid & 31) * 4;         // B: k, n-offset

    float acc[2][4][4] = {};

    // ---- prologue: stage tile 0 into buffer 0 ----
    {
        float4 va = make_float4(0.f, 0.f, 0.f, 0.f);
        if (m0 + ar < NN) va = *(const float4*)(x + (size_t)(m0 + ar) * 256 + ak4);
        u32* da = &As[0][ar][abw];
        da[0] = cvt_tf32(va.x); da[2] = cvt_tf32(va.y);
        da[4] = cvt_tf32(va.z); da[6] = cvt_tf32(va.w);
        #pragma unroll
        for (int rep = 0; rep < 2; rep++) {
            int k = bk + 8 * rep;
            float4 vb = *(const float4*)(We + (size_t)(rb + k) * 256 + cb + bn4);
            u32 w0 = cvt_tf32(vb.x), w1 = cvt_tf32(vb.y), w2 = cvt_tf32(vb.z), w3 = cvt_tf32(vb.w);
            *(uint4*)&Bs[0][k][bn4] = make_uint4(w0, w1, w2, w3);
        }
    }

    int p = 0;
    for (int kt = 0; kt < 16; kt++) {
        __syncthreads();
        const int next = kt + 1;
        float4 va, vb0, vb1;
        if (next < 16) {
            const int k0n = next * 16;
            va = make_float4(0.f, 0.f, 0.f, 0.f);
            if (m0 + ar < NN) va = *(const float4*)(x + (size_t)(m0 + ar) * 256 + k0n + ak4);
            vb0 = *(const float4*)(We + (size_t)(rb + k0n + bk) * 256 + cb + bn4);
            vb1 = *(const float4*)(We + (size_t)(rb + k0n + bk + 8) * 256 + cb + bn4);
        }

        // ---- compute tile kt from buffer p ----
        u32 a[2][2][4];
        #pragma unroll
        for (int mt = 0; mt < 2; mt++) {
            const u64* rL = (const u64*)As[p][wm * 32 + mt * 16 + g];
            const u64* rH = (const u64*)As[p][wm * 32 + mt * 16 + g + 8];
            #pragma unroll
            for (int j = 0; j < 2; j++) {
                upk2u(rL[j * 4 + t], a[mt][j][0], a[mt][j][2]);
                upk2u(rH[j * 4 + t], a[mt][j][1], a[mt][j][3]);
            }
        }
        u32 bf[4][2][2];
        #pragma unroll
        for (int nt = 0; nt < 4; nt++) {
            const int ncol = wn * 32 + nt * 8 + g;
            #pragma unroll
            for (int j = 0; j < 2; j++) {
                bf[nt][j][0] = Bs[p][t + 8 * j][ncol];
                bf[nt][j][1] = Bs[p][t + 4 + 8 * j][ncol];
            }
        }
        #pragma unroll
        for (int mt = 0; mt < 2; mt++)
            #pragma unroll
            for (int nt = 0; nt < 4; nt++)
                #pragma unroll
                for (int j = 0; j < 2; j++)
                    mma_tf32(acc[mt][nt][0], acc[mt][nt][1], acc[mt][nt][2], acc[mt][nt][3],
                             a[mt][j][0], a[mt][j][1], a[mt][j][2], a[mt][j][3],
                             bf[nt][j][0], bf[nt][j][1],
                             acc[mt][nt][0], acc[mt][nt][1], acc[mt][nt][2], acc[mt][nt][3]);

        // ---- stage tile kt+1 into buffer 1-p ----
        if (next < 16) {
            u32* da = &As[1 - p][ar][abw];
            da[0] = cvt_tf32(va.x); da[2] = cvt_tf32(va.y);
            da[4] = cvt_tf32(va.z); da[6] = cvt_tf32(va.w);
            *(uint4*)&Bs[1 - p][bk][bn4] =
                make_uint4(cvt_tf32(vb0.x), cvt_tf32(vb0.y), cvt_tf32(vb0.z), cvt_tf32(vb0.w));
            *(uint4*)&Bs[1 - p][bk + 8][bn4] =
                make_uint4(cvt_tf32(vb1.x), cvt_tf32(vb1.y), cvt_tf32(vb1.z), cvt_tf32(vb1.w));
        }
        p ^= 1;
    }

    #pragma unroll
    for (int mt = 0; mt < 2; mt++) {
        int mrow = m0 + wm * 32 + mt * 16 + g;
        #pragma unroll
        for (int nt = 0; nt < 4; nt++) {
            int col = n0 + wn * 32 + nt * 8 + 2 * t;
            if (mrow < NN)
                *(float2*)(g_YZ + (size_t)mrow * 512 + col) = make_float2(acc[mt][nt][0], acc[mt][nt][1]);
            if (mrow + 8 < NN)
                *(float2*)(g_YZ + (size_t)(mrow + 8) * 512 + col) = make_float2(acc[mt][nt][2], acc[mt][nt][3]);
        }
    }
}

__global__ void zero_s() { g_S[threadIdx.x] = 0.f; }

// ---------------------------------------------------------------------------
// Kernel 3 (v4, unchanged from R5 — measured 182us): tensor-core edge stage
// with permuted column mapping (contiguous 32B gathers, LDG.128, no shuffles).
// ---------------------------------------------------------------------------
__global__ __launch_bounds__(256, 2) void edge_kernel(const void* __restrict__ eraw,
                                                      const float* __restrict__ attrs,
                                                      const float* __restrict__ We,
                                                      const float* __restrict__ b_edge) {
    __shared__ u32 attr_s[NB][32][24];
    __shared__ int sidx_s[32], didx_s[32];
    __shared__ float Ssh[NB * HID];

    const int tid = threadIdx.x;
    for (int i = tid; i < NB * HID; i += 256) Ssh[i] = 0.f;

    const int warp = tid >> 5;
    const int lane = tid & 31;
    const int g = lane >> 2;
    const int t = lane & 3;
    const int hbase = warp * 32;

    u32 Bf[4][2][2];
    const int colB = hbase + 8 * (g >> 1) + (g & 1);
    #pragma unroll
    for (int nt = 0; nt < 4; nt++)
        #pragma unroll
        for (int ks = 0; ks < 2; ks++) {
            Bf[nt][ks][0] = cvt_tf32(We[(512 + t + 8 * ks) * 256 + colB + 2 * nt]);
            Bf[nt][ks][1] = cvt_tf32(We[(512 + t + 4 + 8 * ks) * 256 + colB + 2 * nt]);
        }
    u64 bias4[4];
    {
        const u64* bp = (const u64*)(b_edge + hbase + 8 * t);
        bias4[0] = bp[0]; bias4[1] = bp[1]; bias4[2] = bp[2]; bias4[3] = bp[3];
    }

    const int is64 = g_is_i64;
    const long long* e64 = (const long long*)eraw;
    const int*       e32 = (const int*)eraw;

    u64 acc[NB][4] = {};

    const int nchunks = NE / 32;
    for (int c = blockIdx.x; c < nchunks; c += gridDim.x) {
        const int e0 = c * 32;
        __syncthreads();
        if (tid < 32)      sidx_s[tid]      = is64 ? (int)e64[e0 + tid]           : e32[e0 + tid];
        else if (tid < 64) didx_s[tid - 32] = is64 ? (int)e64[NE + e0 + tid - 32] : e32[NE + e0 + tid - 32];
        {
            int b = tid >> 6, r = tid & 63;
            const float4* src = (const float4*)(attrs + ((size_t)b * NE + e0) * 16);
            #pragma unroll
            for (int k2 = 0; k2 < 2; k2++) {
                float4 v = src[r * 2 + k2];
                int flat = (r * 2 + k2) * 4;
                int e = flat >> 4, a0i = flat & 15;
                int bw = (a0i & 8) + ((a0i & 4) ? 1 : 0);
                u32* dst = &attr_s[b][e][bw];
                dst[0] = cvt_tf32(v.x); dst[2] = cvt_tf32(v.y);
                dst[4] = cvt_tf32(v.z); dst[6] = cvt_tf32(v.w);
            }
        }
        __syncthreads();

        #pragma unroll
        for (int sub = 0; sub < 2; sub++) {
            const int eb = sub * 16;
            const int sl = sidx_s[eb + g],     dl = didx_s[eb + g];
            const int sh = sidx_s[eb + g + 8], dh = didx_s[eb + g + 8];

            const ulonglong2* pyl = (const ulonglong2*)(g_YZ + (size_t)sl * 512 + hbase + 8 * t);
            const ulonglong2* pyh = (const ulonglong2*)(g_YZ + (size_t)sh * 512 + hbase + 8 * t);
            const ulonglong2* pzl = (const ulonglong2*)(g_YZ + (size_t)dl * 512 + 256 + hbase + 8 * t);
            const ulonglong2* pzh = (const ulonglong2*)(g_YZ + (size_t)dh * 512 + 256 + hbase + 8 * t);
            ulonglong2 yl0 = pyl[0], yl1 = pyl[1];
            ulonglong2 yh0 = pyh[0], yh1 = pyh[1];
            ulonglong2 zl0 = pzl[0], zl1 = pzl[1];
            ulonglong2 zh0 = pzh[0], zh1 = pzh[1];

            u64 bLo[4], bHi[4];
            bLo[0] = add2(add2(yl0.x, zl0.x), bias4[0]);
            bLo[1] = add2(add2(yl0.y, zl0.y), bias4[1]);
            bLo[2] = add2(add2(yl1.x, zl1.x), bias4[2]);
            bLo[3] = add2(add2(yl1.y, zl1.y), bias4[3]);
            bHi[0] = add2(add2(yh0.x, zh0.x), bias4[0]);
            bHi[1] = add2(add2(yh0.y, zh0.y), bias4[1]);
            bHi[2] = add2(add2(yh1.x, zh1.x), bias4[2]);
            bHi[3] = add2(add2(yh1.y, zh1.y), bias4[3]);

            #pragma unroll
            for (int b = 0; b < NB; b++) {
                const u64* arL = (const u64*)attr_s[b][eb + g];
                const u64* arH = (const u64*)attr_s[b][eb + g + 8];
                u32 a0, a1, a2, a3, a4, a5, a6, a7;
                upk2u(arL[t],     a0, a2);
                upk2u(arH[t],     a1, a3);
                upk2u(arL[t + 4], a4, a6);
                upk2u(arH[t + 4], a5, a7);
                #pragma unroll
                for (int nt = 0; nt < 4; nt++) {
                    float c0, c1, c2, c3;
                    upk2(bLo[nt], c0, c1);
                    upk2(bHi[nt], c2, c3);
                    float d0, d1, d2, d3;
                    mma_tf32(d0, d1, d2, d3, a0, a1, a2, a3, Bf[nt][0][0], Bf[nt][0][1], c0, c1, c2, c3);
                    mma_tf32(d0, d1, d2, d3, a4, a5, a6, a7, Bf[nt][1][0], Bf[nt][1][1], d0, d1, d2, d3);
                    acc[b][nt] = add2(acc[b][nt], pk2(fmaxf(d0, 0.f), fmaxf(d1, 0.f)));
                    acc[b][nt] = add2(acc[b][nt], pk2(fmaxf(d2, 0.f), fmaxf(d3, 0.f)));
                }
            }
        }
    }

    #pragma unroll
    for (int b = 0; b < NB; b++)
        #pragma unroll
        for (int nt = 0; nt < 4; nt++) {
            u64 v = acc[b][nt];
            v = add2(v, __shfl_down_sync(0xffffffffu, v, 16));
            v = add2(v, __shfl_down_sync(0xffffffffu, v, 8));
            v = add2(v, __shfl_down_sync(0xffffffffu, v, 4));
            acc[b][nt] = v;
        }
    if (lane < 4) {
        #pragma unroll
        for (int b = 0; b < NB; b++)
            #pragma unroll
            for (int nt = 0; nt < 4; nt++) {
                float lo, hi;
                upk2(acc[b][nt], lo, hi);
                int h = hbase + 8 * lane + 2 * nt;
                atomicAdd(&Ssh[b * 256 + h], lo);
                atomicAdd(&Ssh[b * 256 + h + 1], hi);
            }
    }
    __syncthreads();
    for (int i = tid; i < NB * HID; i += 256) atomicAdd(&g_S[i], Ssh[i]);
}

// ---------------------------------------------------------------------------
// Kernel 4: out = (S/NE) @ W_graph + b_graph
// ---------------------------------------------------------------------------
__global__ void final_kernel(const float* __restrict__ Wg,
                             const float* __restrict__ bg,
                             float* __restrict__ out) {
    const int t = threadIdx.x; // 512 threads
    const int b = t >> 7, o = t & 127;
    const float invE = 1.0f / (float)NE;
    float dot = 0.f;
    #pragma unroll 8
    for (int h = 0; h < 256; h++)
        dot += g_S[b * 256 + h] * Wg[h * 128 + o];
    out[t] = fmaf(dot, invE, bg[o]);
}

extern "C" void kernel_launch(void* const* d_in, const int* in_sizes, int n_in,
                              void* d_out, int out_size) {
    const float* x     = (const float*)d_in[0];
    const void*  eidx  = d_in[1];
    const float* attrs = (const float*)d_in[2];
    const float* We    = (const float*)d_in[3];
    const float* be    = (const float*)d_in[4];
    const float* Wg    = (const float*)d_in[5];
    const float* bg    = (const float*)d_in[6];
    float* out = (float*)d_out;

    detect_dtype<<<1, 32>>>(eidx);
    dim3 gn(4, 313);
    node_gemm<<<gn, 256>>>(x, We);
    zero_s<<<1, NB * HID>>>();
    edge_kernel<<<296, 256>>>(eidx, attrs, We, be);
    final_kernel<<<1, 512>>>(Wg, bg, out);
}

// round 7
// speedup vs baseline: 1.9741x; 1.2545x over previous
#include <cuda_runtime.h>

#define NN 20000
#define NE 400000
#define NB 4
#define HID 256
#define OD 128
#define CHUNK 64

__device__ __align__(16) float g_YZ[NN * 512];
__device__ float g_S[NB * HID];
__device__ int g_is_i64;

typedef unsigned long long u64;
typedef unsigned int u32;

__device__ __forceinline__ u64 pk2(float lo, float hi) {
    u64 r;
    asm("mov.b64 %0, {%1, %2};" : "=l"(r) : "r"(__float_as_uint(lo)), "r"(__float_as_uint(hi)));
    return r;
}
__device__ __forceinline__ void upk2(u64 p, float &lo, float &hi) {
    unsigned a, b;
    asm("mov.b64 {%0, %1}, %2;" : "=r"(a), "=r"(b) : "l"(p));
    lo = __uint_as_float(a); hi = __uint_as_float(b);
}
__device__ __forceinline__ void upk2u(u64 p, u32 &lo, u32 &hi) {
    asm("mov.b64 {%0, %1}, %2;" : "=r"(lo), "=r"(hi) : "l"(p));
}
__device__ __forceinline__ u64 add2(u64 a, u64 b) {
    u64 d;
    asm("add.rn.f32x2 %0, %1, %2;" : "=l"(d) : "l"(a), "l"(b));
    return d;
}
__device__ __forceinline__ u32 cvt_tf32(float f) {
    u32 r;
    asm("cvt.rna.tf32.f32 %0, %1;" : "=r"(r) : "f"(f));
    return r;
}
__device__ __forceinline__ void mma_tf32(float &d0, float &d1, float &d2, float &d3,
                                         u32 a0, u32 a1, u32 a2, u32 a3,
                                         u32 b0, u32 b1,
                                         float c0, float c1, float c2, float c3) {
    asm volatile("mma.sync.aligned.m16n8k8.row.col.f32.tf32.tf32.f32 "
                 "{%0,%1,%2,%3}, {%4,%5,%6,%7}, {%8,%9}, {%10,%11,%12,%13};"
                 : "=f"(d0), "=f"(d1), "=f"(d2), "=f"(d3)
                 : "r"(a0), "r"(a1), "r"(a2), "r"(a3), "r"(b0), "r"(b1),
                   "f"(c0), "f"(c1), "f"(c2), "f"(c3));
}
__device__ __forceinline__ u32 smem_u32(const void* p) {
    return (u32)__cvta_generic_to_shared(p);
}

// ---------------------------------------------------------------------------
// Kernel 0: dtype probe (int32 vs int64 edge_index).
// ---------------------------------------------------------------------------
__global__ void detect_dtype(const void* __restrict__ eraw) {
    const long long* p = (const long long*)eraw;
    int lane = threadIdx.x;
    long long v0 = p[lane];
    long long v1 = p[64 + lane];
    bool ok = (v0 >= 0 && v0 < NN) && (v1 >= 0 && v1 < NN);
    unsigned m = __ballot_sync(0xffffffffu, ok);
    if (lane == 0) g_is_i64 = (m == 0xffffffffu) ? 1 : 0;
}

// ---------------------------------------------------------------------------
// Kernel 1 (v3, unchanged from R6 — proven): YZ = x @ [W_src | W_dst],
// tf32 mma, double-buffered, conflict-free smem.
// ---------------------------------------------------------------------------
__global__ __launch_bounds__(256) void node_gemm(const float* __restrict__ x,
                                                 const float* __restrict__ We) {
    __shared__ u32 As[2][64][24];
    __shared__ __align__(16) u32 Bs[2][16][136];

    const int m0 = blockIdx.y * 64;
    const int n0 = blockIdx.x * 128;
    const int rb = (n0 >= 256) ? 256 : 0;
    const int cb = n0 - rb;
    const int tid = threadIdx.x;
    const int warp = tid >> 5, lane = tid & 31, g = lane >> 2, t = lane & 3;
    const int wm = warp >> 2, wn = warp & 3;

    const int ar = tid >> 2, ak4 = (tid & 3) * 4;
    const int abw = (ak4 & 8) + ((ak4 & 4) ? 1 : 0);
    const int bk = tid >> 5, bn4 = (tid & 31) * 4;

    float acc[2][4][4] = {};

    {
        float4 va = make_float4(0.f, 0.f, 0.f, 0.f);
        if (m0 + ar < NN) va = *(const float4*)(x + (size_t)(m0 + ar) * 256 + ak4);
        u32* da = &As[0][ar][abw];
        da[0] = cvt_tf32(va.x); da[2] = cvt_tf32(va.y);
        da[4] = cvt_tf32(va.z); da[6] = cvt_tf32(va.w);
        #pragma unroll
        for (int rep = 0; rep < 2; rep++) {
            int k = bk + 8 * rep;
            float4 vb = *(const float4*)(We + (size_t)(rb + k) * 256 + cb + bn4);
            *(uint4*)&Bs[0][k][bn4] =
                make_uint4(cvt_tf32(vb.x), cvt_tf32(vb.y), cvt_tf32(vb.z), cvt_tf32(vb.w));
        }
    }

    int p = 0;
    for (int kt = 0; kt < 16; kt++) {
        __syncthreads();
        const int next = kt + 1;
        float4 va, vb0, vb1;
        if (next < 16) {
            const int k0n = next * 16;
            va = make_float4(0.f, 0.f, 0.f, 0.f);
            if (m0 + ar < NN) va = *(const float4*)(x + (size_t)(m0 + ar) * 256 + k0n + ak4);
            vb0 = *(const float4*)(We + (size_t)(rb + k0n + bk) * 256 + cb + bn4);
            vb1 = *(const float4*)(We + (size_t)(rb + k0n + bk + 8) * 256 + cb + bn4);
        }

        u32 a[2][2][4];
        #pragma unroll
        for (int mt = 0; mt < 2; mt++) {
            const u64* rL = (const u64*)As[p][wm * 32 + mt * 16 + g];
            const u64* rH = (const u64*)As[p][wm * 32 + mt * 16 + g + 8];
            #pragma unroll
            for (int j = 0; j < 2; j++) {
                upk2u(rL[j * 4 + t], a[mt][j][0], a[mt][j][2]);
                upk2u(rH[j * 4 + t], a[mt][j][1], a[mt][j][3]);
            }
        }
        u32 bf[4][2][2];
        #pragma unroll
        for (int nt = 0; nt < 4; nt++) {
            const int ncol = wn * 32 + nt * 8 + g;
            #pragma unroll
            for (int j = 0; j < 2; j++) {
                bf[nt][j][0] = Bs[p][t + 8 * j][ncol];
                bf[nt][j][1] = Bs[p][t + 4 + 8 * j][ncol];
            }
        }
        #pragma unroll
        for (int mt = 0; mt < 2; mt++)
            #pragma unroll
            for (int nt = 0; nt < 4; nt++)
                #pragma unroll
                for (int j = 0; j < 2; j++)
                    mma_tf32(acc[mt][nt][0], acc[mt][nt][1], acc[mt][nt][2], acc[mt][nt][3],
                             a[mt][j][0], a[mt][j][1], a[mt][j][2], a[mt][j][3],
                             bf[nt][j][0], bf[nt][j][1],
                             acc[mt][nt][0], acc[mt][nt][1], acc[mt][nt][2], acc[mt][nt][3]);

        if (next < 16) {
            u32* da = &As[1 - p][ar][abw];
            da[0] = cvt_tf32(va.x); da[2] = cvt_tf32(va.y);
            da[4] = cvt_tf32(va.z); da[6] = cvt_tf32(va.w);
            *(uint4*)&Bs[1 - p][bk][bn4] =
                make_uint4(cvt_tf32(vb0.x), cvt_tf32(vb0.y), cvt_tf32(vb0.z), cvt_tf32(vb0.w));
            *(uint4*)&Bs[1 - p][bk + 8][bn4] =
                make_uint4(cvt_tf32(vb1.x), cvt_tf32(vb1.y), cvt_tf32(vb1.z), cvt_tf32(vb1.w));
        }
        p ^= 1;
    }

    #pragma unroll
    for (int mt = 0; mt < 2; mt++) {
        int mrow = m0 + wm * 32 + mt * 16 + g;
        #pragma unroll
        for (int nt = 0; nt < 4; nt++) {
            int col = n0 + wn * 32 + nt * 8 + 2 * t;
            if (mrow < NN)
                *(float2*)(g_YZ + (size_t)mrow * 512 + col) = make_float2(acc[mt][nt][0], acc[mt][nt][1]);
            if (mrow + 8 < NN)
                *(float2*)(g_YZ + (size_t)(mrow + 8) * 512 + col) = make_float2(acc[mt][nt][2], acc[mt][nt][3]);
        }
    }
}

__global__ void zero_s() { g_S[threadIdx.x] = 0.f; }

// ---------------------------------------------------------------------------
// Kernel 3 (v5): edge stage, cp.async double-buffered chunks of 64 edges.
// attrs flow gmem->smem raw (fp32 bits fed to tf32 mma = truncation rounding),
// rows stride-20 words (16B-aligned for cp.async, conflict-free LDS).
// Gathers use 32-bit byte offsets. Permuted column mapping as in R5/R6.
// ---------------------------------------------------------------------------
__global__ __launch_bounds__(256, 2) void edge_kernel(const void* __restrict__ eraw,
                                                      const float* __restrict__ attrs,
                                                      const float* __restrict__ We,
                                                      const float* __restrict__ b_edge) {
    __shared__ __align__(16) u32 attr_s[2][NB][CHUNK][20];
    __shared__ int idx_s[2][128];      // [0..63]=src, [64..127]=dst
    __shared__ float Ssh[NB * HID];

    const int tid = threadIdx.x;
    for (int i = tid; i < NB * HID; i += 256) Ssh[i] = 0.f;

    const int warp = tid >> 5, lane = tid & 31, g = lane >> 2, t = lane & 3;
    const int hbase = warp * 32;

    // Persistent B-frags (permuted mapping) + bias
    u32 Bf[4][2][2];
    const int colB = hbase + 8 * (g >> 1) + (g & 1);
    #pragma unroll
    for (int nt = 0; nt < 4; nt++)
        #pragma unroll
        for (int ks = 0; ks < 2; ks++) {
            Bf[nt][ks][0] = cvt_tf32(We[(512 + t + 8 * ks) * 256 + colB + 2 * nt]);
            Bf[nt][ks][1] = cvt_tf32(We[(512 + t + 4 + 8 * ks) * 256 + colB + 2 * nt]);
        }
    u64 bias4[4];
    {
        const u64* bp = (const u64*)(b_edge + hbase + 8 * t);
        bias4[0] = bp[0]; bias4[1] = bp[1]; bias4[2] = bp[2]; bias4[3] = bp[3];
    }

    const int is64 = g_is_i64;
    const long long* e64 = (const long long*)eraw;
    const int*       e32 = (const int*)eraw;

    const char* yzb = (const char*)g_YZ;
    const u32 co = (u32)(hbase + 8 * t) * 4u;   // byte offset of this thread's 32B slice

    // staging roles
    const int sb = tid >> 6, eL = tid & 63;     // attr staging: batch, edge-in-chunk

    u64 acc[NB][4] = {};

    const int nchunks = NE / CHUNK;
    const int stride = gridDim.x;
    int c = blockIdx.x;
    int p = 0;

    // ---- prologue: stage chunk c into buffer 0 ----
    {
        const int e0 = c * CHUNK;
        if (tid < 128) {
            size_t gi = (size_t)(tid >> 6) * NE + e0 + (tid & 63);
            if (is64) idx_s[0][tid] = (int)e64[gi];
            else {
                u32 d = smem_u32(&idx_s[0][tid]);
                asm volatile("cp.async.ca.shared.global [%0], [%1], 4;" :: "r"(d), "l"(e32 + gi));
            }
        }
        const float* src = attrs + ((size_t)sb * NE + e0 + eL) * 16;
        u32 d = smem_u32(&attr_s[0][sb][eL][0]);
        #pragma unroll
        for (int j = 0; j < 4; j++)
            asm volatile("cp.async.cg.shared.global [%0], [%1], 16;" :: "r"(d + j * 16), "l"(src + j * 4));
        asm volatile("cp.async.commit_group;");
    }

    for (; c < nchunks; c += stride) {
        const int cn = c + stride;
        if (cn < nchunks) {
            // stage next chunk into buffer 1-p
            const int e0n = cn * CHUNK;
            if (tid < 128) {
                size_t gi = (size_t)(tid >> 6) * NE + e0n + (tid & 63);
                if (is64) idx_s[1 - p][tid] = (int)e64[gi];
                else {
                    u32 d = smem_u32(&idx_s[1 - p][tid]);
                    asm volatile("cp.async.ca.shared.global [%0], [%1], 4;" :: "r"(d), "l"(e32 + gi));
                }
            }
            const float* src = attrs + ((size_t)sb * NE + e0n + eL) * 16;
            u32 d = smem_u32(&attr_s[1 - p][sb][eL][0]);
            #pragma unroll
            for (int j = 0; j < 4; j++)
                asm volatile("cp.async.cg.shared.global [%0], [%1], 16;" :: "r"(d + j * 16), "l"(src + j * 4));
            asm volatile("cp.async.commit_group;");
            asm volatile("cp.async.wait_group 1;");
        } else {
            asm volatile("cp.async.wait_group 0;");
        }
        __syncthreads();   // staged data of buffer p visible to all warps

        #pragma unroll 1
        for (int sub = 0; sub < 4; sub++) {
            const int eb = sub * 16;
            const int sl = idx_s[p][eb + g],      dl = idx_s[p][64 + eb + g];
            const int sh = idx_s[p][eb + g + 8],  dh = idx_s[p][64 + eb + g + 8];

            const u32 oyl = (u32)sl * 2048u + co;
            const u32 oyh = (u32)sh * 2048u + co;
            const u32 ozl = (u32)dl * 2048u + 1024u + co;
            const u32 ozh = (u32)dh * 2048u + 1024u + co;
            ulonglong2 yl0 = *(const ulonglong2*)(yzb + oyl);
            ulonglong2 yl1 = *(const ulonglong2*)(yzb + oyl + 16);
            ulonglong2 yh0 = *(const ulonglong2*)(yzb + oyh);
            ulonglong2 yh1 = *(const ulonglong2*)(yzb + oyh + 16);
            ulonglong2 zl0 = *(const ulonglong2*)(yzb + ozl);
            ulonglong2 zl1 = *(const ulonglong2*)(yzb + ozl + 16);
            ulonglong2 zh0 = *(const ulonglong2*)(yzb + ozh);
            ulonglong2 zh1 = *(const ulonglong2*)(yzb + ozh + 16);

            u64 bLo[4], bHi[4];
            bLo[0] = add2(add2(yl0.x, zl0.x), bias4[0]);
            bLo[1] = add2(add2(yl0.y, zl0.y), bias4[1]);
            bLo[2] = add2(add2(yl1.x, zl1.x), bias4[2]);
            bLo[3] = add2(add2(yl1.y, zl1.y), bias4[3]);
            bHi[0] = add2(add2(yh0.x, zh0.x), bias4[0]);
            bHi[1] = add2(add2(yh0.y, zh0.y), bias4[1]);
            bHi[2] = add2(add2(yh1.x, zh1.x), bias4[2]);
            bHi[3] = add2(add2(yh1.y, zh1.y), bias4[3]);

            #pragma unroll
            for (int b = 0; b < NB; b++) {
                const u32* arL = attr_s[p][b][eb + g];
                const u32* arH = attr_s[p][b][eb + g + 8];
                u32 a0 = arL[t],      a1 = arH[t];
                u32 a2 = arL[t + 4],  a3 = arH[t + 4];
                u32 a4 = arL[t + 8],  a5 = arH[t + 8];
                u32 a6 = arL[t + 12], a7 = arH[t + 12];
                #pragma unroll
                for (int nt = 0; nt < 4; nt++) {
                    float c0, c1, c2, c3;
                    upk2(bLo[nt], c0, c1);
                    upk2(bHi[nt], c2, c3);
                    float d0, d1, d2, d3;
                    mma_tf32(d0, d1, d2, d3, a0, a1, a2, a3, Bf[nt][0][0], Bf[nt][0][1], c0, c1, c2, c3);
                    mma_tf32(d0, d1, d2, d3, a4, a5, a6, a7, Bf[nt][1][0], Bf[nt][1][1], d0, d1, d2, d3);
                    acc[b][nt] = add2(acc[b][nt], pk2(fmaxf(d0, 0.f), fmaxf(d1, 0.f)));
                    acc[b][nt] = add2(acc[b][nt], pk2(fmaxf(d2, 0.f), fmaxf(d3, 0.f)));
                }
            }
        }
        __syncthreads();   // all warps done with buffer p before restaging it
        p ^= 1;
    }

    // ---- reduce over g (fixed t), write under permuted mapping ----
    #pragma unroll
    for (int b = 0; b < NB; b++)
        #pragma unroll
        for (int nt = 0; nt < 4; nt++) {
            u64 v = acc[b][nt];
            v = add2(v, __shfl_down_sync(0xffffffffu, v, 16));
            v = add2(v, __shfl_down_sync(0xffffffffu, v, 8));
            v = add2(v, __shfl_down_sync(0xffffffffu, v, 4));
            acc[b][nt] = v;
        }
    if (lane < 4) {
        #pragma unroll
        for (int b = 0; b < NB; b++)
            #pragma unroll
            for (int nt = 0; nt < 4; nt++) {
                float lo, hi;
                upk2(acc[b][nt], lo, hi);
                int h = hbase + 8 * lane + 2 * nt;
                atomicAdd(&Ssh[b * 256 + h], lo);
                atomicAdd(&Ssh[b * 256 + h + 1], hi);
            }
    }
    __syncthreads();
    for (int i = tid; i < NB * HID; i += 256) atomicAdd(&g_S[i], Ssh[i]);
}

// ---------------------------------------------------------------------------
// Kernel 4: out = (S/NE) @ W_graph + b_graph
// ---------------------------------------------------------------------------
__global__ void final_kernel(const float* __restrict__ Wg,
                             const float* __restrict__ bg,
                             float* __restrict__ out) {
    const int t = threadIdx.x; // 512 threads
    const int b = t >> 7, o = t & 127;
    const float invE = 1.0f / (float)NE;
    float dot = 0.f;
    #pragma unroll 8
    for (int h = 0; h < 256; h++)
        dot += g_S[b * 256 + h] * Wg[h * 128 + o];
    out[t] = fmaf(dot, invE, bg[o]);
}

extern "C" void kernel_launch(void* const* d_in, const int* in_sizes, int n_in,
                              void* d_out, int out_size) {
    const float* x     = (const float*)d_in[0];
    const void*  eidx  = d_in[1];
    const float* attrs = (const float*)d_in[2];
    const float* We    = (const float*)d_in[3];
    const float* be    = (const float*)d_in[4];
    const float* Wg    = (const float*)d_in[5];
    const float* bg    = (const float*)d_in[6];
    float* out = (float*)d_out;

    detect_dtype<<<1, 32>>>(eidx);
    dim3 gn(4, 313);
    node_gemm<<<gn, 256>>>(x, We);
    zero_s<<<1, NB * HID>>>();
    edge_kernel<<<296, 256>>>(eidx, attrs, We, be);
    final_kernel<<<1, 512>>>(Wg, bg, out);
}

// round 9
// speedup vs baseline: 1.9941x; 1.0101x over previous
#include <cuda_runtime.h>

typedef unsigned long long u64;
typedef unsigned int u32;

#define NN 20000
#define NE 400000
#define NB 4
#define HID 256
#define OD 128
#define CHUNK 64

// YZ table in bf16 pairs: row = 512 bf16 = 256 u32 words = 1024 bytes.
__device__ __align__(16) u32 g_YZ[NN * 256];
__device__ float g_S[NB * HID];
__device__ int g_is_i64;

__device__ __forceinline__ u64 pk2(float lo, float hi) {
    u64 r;
    asm("mov.b64 %0, {%1, %2};" : "=l"(r) : "r"(__float_as_uint(lo)), "r"(__float_as_uint(hi)));
    return r;
}
__device__ __forceinline__ void upk2(u64 p, float &lo, float &hi) {
    unsigned a, b;
    asm("mov.b64 {%0, %1}, %2;" : "=r"(a), "=r"(b) : "l"(p));
    lo = __uint_as_float(a); hi = __uint_as_float(b);
}
__device__ __forceinline__ void upk2u(u64 p, u32 &lo, u32 &hi) {
    asm("mov.b64 {%0, %1}, %2;" : "=r"(lo), "=r"(hi) : "l"(p));
}
__device__ __forceinline__ u64 add2(u64 a, u64 b) {
    u64 d;
    asm("add.rn.f32x2 %0, %1, %2;" : "=l"(d) : "l"(a), "l"(b));
    return d;
}
// expand packed bf16x2 (lo=col c, hi=col c+1) into f32x2 u64 (low lane = col c)
__device__ __forceinline__ u64 bf2f2(u32 v) {
    u32 lo = v << 16;
    u32 hi = v & 0xffff0000u;
    u64 r;
    asm("mov.b64 %0, {%1, %2};" : "=l"(r) : "r"(lo), "r"(hi));
    return r;
}
__device__ __forceinline__ u32 f2bf2(float lo, float hi) {
    u32 r;
    asm("cvt.rn.bf16x2.f32 %0, %1, %2;" : "=r"(r) : "f"(hi), "f"(lo)); // d[15:0]=lo arg last
    return r;
}
__device__ __forceinline__ u32 cvt_tf32(float f) {
    u32 r;
    asm("cvt.rna.tf32.f32 %0, %1;" : "=r"(r) : "f"(f));
    return r;
}
__device__ __forceinline__ void mma_tf32(float &d0, float &d1, float &d2, float &d3,
                                         u32 a0, u32 a1, u32 a2, u32 a3,
                                         u32 b0, u32 b1,
                                         float c0, float c1, float c2, float c3) {
    asm volatile("mma.sync.aligned.m16n8k8.row.col.f32.tf32.tf32.f32 "
                 "{%0,%1,%2,%3}, {%4,%5,%6,%7}, {%8,%9}, {%10,%11,%12,%13};"
                 : "=f"(d0), "=f"(d1), "=f"(d2), "=f"(d3)
                 : "r"(a0), "r"(a1), "r"(a2), "r"(a3), "r"(b0), "r"(b1),
                   "f"(c0), "f"(c1), "f"(c2), "f"(c3));
}
__device__ __forceinline__ u32 smem_u32(const void* p) {
    return (u32)__cvta_generic_to_shared(p);
}

// ---------------------------------------------------------------------------
// Kernel 0: dtype probe (int32 vs int64 edge_index).
// ---------------------------------------------------------------------------
__global__ void detect_dtype(const void* __restrict__ eraw) {
    const long long* p = (const long long*)eraw;
    int lane = threadIdx.x;
    long long v0 = p[lane];
    long long v1 = p[64 + lane];
    bool ok = (v0 >= 0 && v0 < NN) && (v1 >= 0 && v1 < NN);
    unsigned m = __ballot_sync(0xffffffffu, ok);
    if (lane == 0) g_is_i64 = (m == 0xffffffffu) ? 1 : 0;
}

// ---------------------------------------------------------------------------
// Kernel 1: YZ = x @ [W_src | W_dst], tf32 mma, double-buffered; bf16 output.
// ---------------------------------------------------------------------------
__global__ __launch_bounds__(256) void node_gemm(const float* __restrict__ x,
                                                 const float* __restrict__ We) {
    __shared__ u32 As[2][64][24];
    __shared__ __align__(16) u32 Bs[2][16][136];

    const int m0 = blockIdx.y * 64;
    const int n0 = blockIdx.x * 128;
    const int rb = (n0 >= 256) ? 256 : 0;
    const int cb = n0 - rb;
    const int tid = threadIdx.x;
    const int warp = tid >> 5, lane = tid & 31, g = lane >> 2, t = lane & 3;
    const int wm = warp >> 2, wn = warp & 3;

    const int ar = tid >> 2, ak4 = (tid & 3) * 4;
    const int abw = (ak4 & 8) + ((ak4 & 4) ? 1 : 0);
    const int bk = tid >> 5, bn4 = (tid & 31) * 4;

    float acc[2][4][4] = {};

    {
        float4 va = make_float4(0.f, 0.f, 0.f, 0.f);
        if (m0 + ar < NN) va = *(const float4*)(x + (size_t)(m0 + ar) * 256 + ak4);
        u32* da = &As[0][ar][abw];
        da[0] = cvt_tf32(va.x); da[2] = cvt_tf32(va.y);
        da[4] = cvt_tf32(va.z); da[6] = cvt_tf32(va.w);
        #pragma unroll
        for (int rep = 0; rep < 2; rep++) {
            int k = bk + 8 * rep;
            float4 vb = *(const float4*)(We + (size_t)(rb + k) * 256 + cb + bn4);
            *(uint4*)&Bs[0][k][bn4] =
                make_uint4(cvt_tf32(vb.x), cvt_tf32(vb.y), cvt_tf32(vb.z), cvt_tf32(vb.w));
        }
    }

    int p = 0;
    for (int kt = 0; kt < 16; kt++) {
        __syncthreads();
        const int next = kt + 1;
        float4 va, vb0, vb1;
        if (next < 16) {
            const int k0n = next * 16;
            va = make_float4(0.f, 0.f, 0.f, 0.f);
            if (m0 + ar < NN) va = *(const float4*)(x + (size_t)(m0 + ar) * 256 + k0n + ak4);
            vb0 = *(const float4*)(We + (size_t)(rb + k0n + bk) * 256 + cb + bn4);
            vb1 = *(const float4*)(We + (size_t)(rb + k0n + bk + 8) * 256 + cb + bn4);
        }

        u32 a[2][2][4];
        #pragma unroll
        for (int mt = 0; mt < 2; mt++) {
            const u64* rL = (const u64*)As[p][wm * 32 + mt * 16 + g];
            const u64* rH = (const u64*)As[p][wm * 32 + mt * 16 + g + 8];
            #pragma unroll
            for (int j = 0; j < 2; j++) {
                upk2u(rL[j * 4 + t], a[mt][j][0], a[mt][j][2]);
                upk2u(rH[j * 4 + t], a[mt][j][1], a[mt][j][3]);
            }
        }
        u32 bf[4][2][2];
        #pragma unroll
        for (int nt = 0; nt < 4; nt++) {
            const int ncol = wn * 32 + nt * 8 + g;
            #pragma unroll
            for (int j = 0; j < 2; j++) {
                bf[nt][j][0] = Bs[p][t + 8 * j][ncol];
                bf[nt][j][1] = Bs[p][t + 4 + 8 * j][ncol];
            }
        }
        #pragma unroll
        for (int mt = 0; mt < 2; mt++)
            #pragma unroll
            for (int nt = 0; nt < 4; nt++)
                #pragma unroll
                for (int j = 0; j < 2; j++)
                    mma_tf32(acc[mt][nt][0], acc[mt][nt][1], acc[mt][nt][2], acc[mt][nt][3],
                             a[mt][j][0], a[mt][j][1], a[mt][j][2], a[mt][j][3],
                             bf[nt][j][0], bf[nt][j][1],
                             acc[mt][nt][0], acc[mt][nt][1], acc[mt][nt][2], acc[mt][nt][3]);

        if (next < 16) {
            u32* da = &As[1 - p][ar][abw];
            da[0] = cvt_tf32(va.x); da[2] = cvt_tf32(va.y);
            da[4] = cvt_tf32(va.z); da[6] = cvt_tf32(va.w);
            *(uint4*)&Bs[1 - p][bk][bn4] =
                make_uint4(cvt_tf32(vb0.x), cvt_tf32(vb0.y), cvt_tf32(vb0.z), cvt_tf32(vb0.w));
            *(uint4*)&Bs[1 - p][bk + 8][bn4] =
                make_uint4(cvt_tf32(vb1.x), cvt_tf32(vb1.y), cvt_tf32(vb1.z), cvt_tf32(vb1.w));
        }
        p ^= 1;
    }

    // epilogue: pack f32 pairs -> bf16x2 words, store u32 per (row, col-pair)
    #pragma unroll
    for (int mt = 0; mt < 2; mt++) {
        int mrow = m0 + wm * 32 + mt * 16 + g;
        #pragma unroll
        for (int nt = 0; nt < 4; nt++) {
            int colw = (n0 + wn * 32 + nt * 8 + 2 * t) >> 1; // u32 word index in row
            if (mrow < NN)
                g_YZ[(size_t)mrow * 256 + colw] = f2bf2(acc[mt][nt][0], acc[mt][nt][1]);
            if (mrow + 8 < NN)
                g_YZ[(size_t)(mrow + 8) * 256 + colw] = f2bf2(acc[mt][nt][2], acc[mt][nt][3]);
        }
    }
}

__global__ void zero_s() { g_S[threadIdx.x] = 0.f; }

// ---------------------------------------------------------------------------
// Kernel 3 (v6): edge stage; bf16 YZ gathers (1 LDG.128 per row slice, half
// the L1 wavefronts of R7), cp.async double-buffered attrs, permuted cols.
// ---------------------------------------------------------------------------
__global__ __launch_bounds__(256, 2) void edge_kernel(const void* __restrict__ eraw,
                                                      const float* __restrict__ attrs,
                                                      const float* __restrict__ We,
                                                      const float* __restrict__ b_edge) {
    __shared__ __align__(16) u32 attr_s[2][NB][CHUNK][20];
    __shared__ int idx_s[2][128];      // [0..63]=src, [64..127]=dst
    __shared__ float Ssh[NB * HID];

    const int tid = threadIdx.x;
    for (int i = tid; i < NB * HID; i += 256) Ssh[i] = 0.f;

    const int warp = tid >> 5, lane = tid & 31, g = lane >> 2, t = lane & 3;
    const int hbase = warp * 32;

    u32 Bf[4][2][2];
    const int colB = hbase + 8 * (g >> 1) + (g & 1);
    #pragma unroll
    for (int nt = 0; nt < 4; nt++)
        #pragma unroll
        for (int ks = 0; ks < 2; ks++) {
            Bf[nt][ks][0] = cvt_tf32(We[(512 + t + 8 * ks) * 256 + colB + 2 * nt]);
            Bf[nt][ks][1] = cvt_tf32(We[(512 + t + 4 + 8 * ks) * 256 + colB + 2 * nt]);
        }
    u64 bias4[4];
    {
        const u64* bp = (const u64*)(b_edge + hbase + 8 * t);
        bias4[0] = bp[0]; bias4[1] = bp[1]; bias4[2] = bp[2]; bias4[3] = bp[3];
    }

    const int is64 = g_is_i64;
    const long long* e64 = (const long long*)eraw;
    const int*       e32 = (const int*)eraw;

    const char* yzb = (const char*)g_YZ;
    const u32 co = (u32)(hbase + 8 * t) * 2u;   // byte offset of thread's 16B bf16 slice

    const int sb = tid >> 6, eL = tid & 63;

    u64 acc[NB][4] = {};

    const int nchunks = NE / CHUNK;
    const int stride = gridDim.x;
    int c = blockIdx.x;
    int p = 0;

    {
        const int e0 = c * CHUNK;
        if (tid < 128) {
            size_t gi = (size_t)(tid >> 6) * NE + e0 + (tid & 63);
            if (is64) idx_s[0][tid] = (int)e64[gi];
            else {
                u32 d = smem_u32(&idx_s[0][tid]);
                asm volatile("cp.async.ca.shared.global [%0], [%1], 4;" :: "r"(d), "l"(e32 + gi));
            }
        }
        const float* src = attrs + ((size_t)sb * NE + e0 + eL) * 16;
        u32 d = smem_u32(&attr_s[0][sb][eL][0]);
        #pragma unroll
        for (int j = 0; j < 4; j++)
            asm volatile("cp.async.cg.shared.global [%0], [%1], 16;" :: "r"(d + j * 16), "l"(src + j * 4));
        asm volatile("cp.async.commit_group;");
    }

    for (; c < nchunks; c += stride) {
        const int cn = c + stride;
        if (cn < nchunks) {
            const int e0n = cn * CHUNK;
            if (tid < 128) {
                size_t gi = (size_t)(tid >> 6) * NE + e0n + (tid & 63);
                if (is64) idx_s[1 - p][tid] = (int)e64[gi];
                else {
                    u32 d = smem_u32(&idx_s[1 - p][tid]);
                    asm volatile("cp.async.ca.shared.global [%0], [%1], 4;" :: "r"(d), "l"(e32 + gi));
                }
            }
            const float* src = attrs + ((size_t)sb * NE + e0n + eL) * 16;
            u32 d = smem_u32(&attr_s[1 - p][sb][eL][0]);
            #pragma unroll
            for (int j = 0; j < 4; j++)
                asm volatile("cp.async.cg.shared.global [%0], [%1], 16;" :: "r"(d + j * 16), "l"(src + j * 4));
            asm volatile("cp.async.commit_group;");
            asm volatile("cp.async.wait_group 1;");
        } else {
            asm volatile("cp.async.wait_group 0;");
        }
        __syncthreads();

        #pragma unroll 1
        for (int sub = 0; sub < 4; sub++) {
            const int eb = sub * 16;
            const int sl = idx_s[p][eb + g],      dl = idx_s[p][64 + eb + g];
            const int sh = idx_s[p][eb + g + 8],  dh = idx_s[p][64 + eb + g + 8];

            // bf16 gathers: one LDG.128 per row slice
            uint4 yl = *(const uint4*)(yzb + ((u32)sl * 1024u + co));
            uint4 yh = *(const uint4*)(yzb + ((u32)sh * 1024u + co));
            uint4 zl = *(const uint4*)(yzb + ((u32)dl * 1024u + 512u + co));
            uint4 zh = *(const uint4*)(yzb + ((u32)dh * 1024u + 512u + co));

            u64 bLo[4], bHi[4];
            bLo[0] = add2(add2(bf2f2(yl.x), bf2f2(zl.x)), bias4[0]);
            bLo[1] = add2(add2(bf2f2(yl.y), bf2f2(zl.y)), bias4[1]);
            bLo[2] = add2(add2(bf2f2(yl.z), bf2f2(zl.z)), bias4[2]);
            bLo[3] = add2(add2(bf2f2(yl.w), bf2f2(zl.w)), bias4[3]);
            bHi[0] = add2(add2(bf2f2(yh.x), bf2f2(zh.x)), bias4[0]);
            bHi[1] = add2(add2(bf2f2(yh.y), bf2f2(zh.y)), bias4[1]);
            bHi[2] = add2(add2(bf2f2(yh.z), bf2f2(zh.z)), bias4[2]);
            bHi[3] = add2(add2(bf2f2(yh.w), bf2f2(zh.w)), bias4[3]);

            #pragma unroll
            for (int b = 0; b < NB; b++) {
                const u32* arL = attr_s[p][b][eb + g];
                const u32* arH = attr_s[p][b][eb + g + 8];
                u32 a0 = arL[t],      a1 = arH[t];
                u32 a2 = arL[t + 4],  a3 = arH[t + 4];
                u32 a4 = arL[t + 8],  a5 = arH[t + 8];
                u32 a6 = arL[t + 12], a7 = arH[t + 12];
                #pragma unroll
                for (int nt = 0; nt < 4; nt++) {
                    float c0, c1, c2, c3;
                    upk2(bLo[nt], c0, c1);
                    upk2(bHi[nt], c2, c3);
                    float d0, d1, d2, d3;
                    mma_tf32(d0, d1, d2, d3, a0, a1, a2, a3, Bf[nt][0][0], Bf[nt][0][1], c0, c1, c2, c3);
                    mma_tf32(d0, d1, d2, d3, a4, a5, a6, a7, Bf[nt][1][0], Bf[nt][1][1], d0, d1, d2, d3);
                    acc[b][nt] = add2(acc[b][nt], pk2(fmaxf(d0, 0.f), fmaxf(d1, 0.f)));
                    acc[b][nt] = add2(acc[b][nt], pk2(fmaxf(d2, 0.f), fmaxf(d3, 0.f)));
                }
            }
        }
        __syncthreads();
        p ^= 1;
    }

    #pragma unroll
    for (int b = 0; b < NB; b++)
        #pragma unroll
        for (int nt = 0; nt < 4; nt++) {
            u64 v = acc[b][nt];
            v = add2(v, __shfl_down_sync(0xffffffffu, v, 16));
            v = add2(v, __shfl_down_sync(0xffffffffu, v, 8));
            v = add2(v, __shfl_down_sync(0xffffffffu, v, 4));
            acc[b][nt] = v;
        }
    if (lane < 4) {
        #pragma unroll
        for (int b = 0; b < NB; b++)
            #pragma unroll
            for (int nt = 0; nt < 4; nt++) {
                float lo, hi;
                upk2(acc[b][nt], lo, hi);
                int h = hbase + 8 * lane + 2 * nt;
                atomicAdd(&Ssh[b * 256 + h], lo);
                atomicAdd(&Ssh[b * 256 + h + 1], hi);
            }
    }
    __syncthreads();
    for (int i = tid; i < NB * HID; i += 256) atomicAdd(&g_S[i], Ssh[i]);
}

// ---------------------------------------------------------------------------
// Kernel 4: out = (S/NE) @ W_graph + b_graph
// ---------------------------------------------------------------------------
__global__ void final_kernel(const float* __restrict__ Wg,
                             const float* __restrict__ bg,
                             float* __restrict__ out) {
    const int t = threadIdx.x; // 512 threads
    const int b = t >> 7, o = t & 127;
    const float invE = 1.0f / (float)NE;
    float dot = 0.f;
    #pragma unroll 8
    for (int h = 0; h < 256; h++)
        dot += g_S[b * 256 + h] * Wg[h * 128 + o];
    out[t] = fmaf(dot, invE, bg[o]);
}

extern "C" void kernel_launch(void* const* d_in, const int* in_sizes, int n_in,
                              void* d_out, int out_size) {
    const float* x     = (const float*)d_in[0];
    const void*  eidx  = d_in[1];
    const float* attrs = (const float*)d_in[2];
    const float* We    = (const float*)d_in[3];
    const float* be    = (const float*)d_in[4];
    const float* Wg    = (const float*)d_in[5];
    const float* bg    = (const float*)d_in[6];
    float* out = (float*)d_out;

    detect_dtype<<<1, 32>>>(eidx);
    dim3 gn(4, 313);
    node_gemm<<<gn, 256>>>(x, We);
    zero_s<<<1, NB * HID>>>();
    edge_kernel<<<296, 256>>>(eidx, attrs, We, be);
    final_kernel<<<1, 512>>>(Wg, bg, out);
}

// round 10
// speedup vs baseline: 2.0553x; 1.0307x over previous
#include <cuda_runtime.h>

typedef unsigned long long u64;
typedef unsigned int u32;

#define NN 20000
#define NE 400000
#define NB 4
#define HID 256
#define OD 128
#define CHUNK 64

// YZ table in bf16 pairs: row = 512 bf16 = 256 u32 words = 1024 bytes.
// Y half (cols 0..255) has b_edge folded in.
__device__ __align__(16) u32 g_YZ[NN * 256];
__device__ float g_S[NB * HID];
__device__ int g_is_i64;

__device__ __forceinline__ u64 pk2(float lo, float hi) {
    u64 r;
    asm("mov.b64 %0, {%1, %2};" : "=l"(r) : "r"(__float_as_uint(lo)), "r"(__float_as_uint(hi)));
    return r;
}
__device__ __forceinline__ void upk2(u64 p, float &lo, float &hi) {
    unsigned a, b;
    asm("mov.b64 {%0, %1}, %2;" : "=r"(a), "=r"(b) : "l"(p));
    lo = __uint_as_float(a); hi = __uint_as_float(b);
}
__device__ __forceinline__ void upk2u(u64 p, u32 &lo, u32 &hi) {
    asm("mov.b64 {%0, %1}, %2;" : "=r"(lo), "=r"(hi) : "l"(p));
}
__device__ __forceinline__ u64 add2(u64 a, u64 b) {
    u64 d;
    asm("add.rn.f32x2 %0, %1, %2;" : "=l"(d) : "l"(a), "l"(b));
    return d;
}
__device__ __forceinline__ u32 hadd2bf(u32 a, u32 b) {
    u32 d;
    asm("add.rn.bf16x2 %0, %1, %2;" : "=r"(d) : "r"(a), "r"(b));
    return d;
}
// expand packed bf16x2 (lo=col c, hi=col c+1) into f32x2 u64 (low lane = col c)
__device__ __forceinline__ u64 bf2f2(u32 v) {
    u32 lo = v << 16;
    u32 hi = v & 0xffff0000u;
    u64 r;
    asm("mov.b64 %0, {%1, %2};" : "=l"(r) : "r"(lo), "r"(hi));
    return r;
}
__device__ __forceinline__ u32 f2bf2(float lo, float hi) {
    u32 r;
    asm("cvt.rn.bf16x2.f32 %0, %1, %2;" : "=r"(r) : "f"(hi), "f"(lo)); // d[15:0]=lo arg last
    return r;
}
__device__ __forceinline__ u32 cvt_tf32(float f) {
    u32 r;
    asm("cvt.rna.tf32.f32 %0, %1;" : "=r"(r) : "f"(f));
    return r;
}
__device__ __forceinline__ void mma_tf32(float &d0, float &d1, float &d2, float &d3,
                                         u32 a0, u32 a1, u32 a2, u32 a3,
                                         u32 b0, u32 b1,
                                         float c0, float c1, float c2, float c3) {
    asm volatile("mma.sync.aligned.m16n8k8.row.col.f32.tf32.tf32.f32 "
                 "{%0,%1,%2,%3}, {%4,%5,%6,%7}, {%8,%9}, {%10,%11,%12,%13};"
                 : "=f"(d0), "=f"(d1), "=f"(d2), "=f"(d3)
                 : "r"(a0), "r"(a1), "r"(a2), "r"(a3), "r"(b0), "r"(b1),
                   "f"(c0), "f"(c1), "f"(c2), "f"(c3));
}
__device__ __forceinline__ u32 smem_u32(const void* p) {
    return (u32)__cvta_generic_to_shared(p);
}

// ---------------------------------------------------------------------------
// Kernel 0: dtype probe (int32 vs int64 edge_index).
// ---------------------------------------------------------------------------
__global__ void detect_dtype(const void* __restrict__ eraw) {
    const long long* p = (const long long*)eraw;
    int lane = threadIdx.x;
    long long v0 = p[lane];
    long long v1 = p[64 + lane];
    bool ok = (v0 >= 0 && v0 < NN) && (v1 >= 0 && v1 < NN);
    unsigned m = __ballot_sync(0xffffffffu, ok);
    if (lane == 0) g_is_i64 = (m == 0xffffffffu) ? 1 : 0;
}

// ---------------------------------------------------------------------------
// Kernel 1: YZ = x @ [W_src | W_dst] (+ b_edge folded into Y half),
// tf32 mma, double-buffered; bf16 output.
// ---------------------------------------------------------------------------
__global__ __launch_bounds__(256) void node_gemm(const float* __restrict__ x,
                                                 const float* __restrict__ We,
                                                 const float* __restrict__ b_edge) {
    __shared__ u32 As[2][64][24];
    __shared__ __align__(16) u32 Bs[2][16][136];

    const int m0 = blockIdx.y * 64;
    const int n0 = blockIdx.x * 128;
    const int rb = (n0 >= 256) ? 256 : 0;
    const int cb = n0 - rb;
    const int tid = threadIdx.x;
    const int warp = tid >> 5, lane = tid & 31, g = lane >> 2, t = lane & 3;
    const int wm = warp >> 2, wn = warp & 3;

    const int ar = tid >> 2, ak4 = (tid & 3) * 4;
    const int abw = (ak4 & 8) + ((ak4 & 4) ? 1 : 0);
    const int bk = tid >> 5, bn4 = (tid & 31) * 4;

    float acc[2][4][4] = {};

    {
        float4 va = make_float4(0.f, 0.f, 0.f, 0.f);
        if (m0 + ar < NN) va = *(const float4*)(x + (size_t)(m0 + ar) * 256 + ak4);
        u32* da = &As[0][ar][abw];
        da[0] = cvt_tf32(va.x); da[2] = cvt_tf32(va.y);
        da[4] = cvt_tf32(va.z); da[6] = cvt_tf32(va.w);
        #pragma unroll
        for (int rep = 0; rep < 2; rep++) {
            int k = bk + 8 * rep;
            float4 vb = *(const float4*)(We + (size_t)(rb + k) * 256 + cb + bn4);
            *(uint4*)&Bs[0][k][bn4] =
                make_uint4(cvt_tf32(vb.x), cvt_tf32(vb.y), cvt_tf32(vb.z), cvt_tf32(vb.w));
        }
    }

    int p = 0;
    for (int kt = 0; kt < 16; kt++) {
        __syncthreads();
        const int next = kt + 1;
        float4 va, vb0, vb1;
        if (next < 16) {
            const int k0n = next * 16;
            va = make_float4(0.f, 0.f, 0.f, 0.f);
            if (m0 + ar < NN) va = *(const float4*)(x + (size_t)(m0 + ar) * 256 + k0n + ak4);
            vb0 = *(const float4*)(We + (size_t)(rb + k0n + bk) * 256 + cb + bn4);
            vb1 = *(const float4*)(We + (size_t)(rb + k0n + bk + 8) * 256 + cb + bn4);
        }

        u32 a[2][2][4];
        #pragma unroll
        for (int mt = 0; mt < 2; mt++) {
            const u64* rL = (const u64*)As[p][wm * 32 + mt * 16 + g];
            const u64* rH = (const u64*)As[p][wm * 32 + mt * 16 + g + 8];
            #pragma unroll
            for (int j = 0; j < 2; j++) {
                upk2u(rL[j * 4 + t], a[mt][j][0], a[mt][j][2]);
                upk2u(rH[j * 4 + t], a[mt][j][1], a[mt][j][3]);
            }
        }
        u32 bf[4][2][2];
        #pragma unroll
        for (int nt = 0; nt < 4; nt++) {
            const int ncol = wn * 32 + nt * 8 + g;
            #pragma unroll
            for (int j = 0; j < 2; j++) {
                bf[nt][j][0] = Bs[p][t + 8 * j][ncol];
                bf[nt][j][1] = Bs[p][t + 4 + 8 * j][ncol];
            }
        }
        #pragma unroll
        for (int mt = 0; mt < 2; mt++)
            #pragma unroll
            for (int nt = 0; nt < 4; nt++)
                #pragma unroll
                for (int j = 0; j < 2; j++)
                    mma_tf32(acc[mt][nt][0], acc[mt][nt][1], acc[mt][nt][2], acc[mt][nt][3],
                             a[mt][j][0], a[mt][j][1], a[mt][j][2], a[mt][j][3],
                             bf[nt][j][0], bf[nt][j][1],
                             acc[mt][nt][0], acc[mt][nt][1], acc[mt][nt][2], acc[mt][nt][3]);

        if (next < 16) {
            u32* da = &As[1 - p][ar][abw];
            da[0] = cvt_tf32(va.x); da[2] = cvt_tf32(va.y);
            da[4] = cvt_tf32(va.z); da[6] = cvt_tf32(va.w);
            *(uint4*)&Bs[1 - p][bk][bn4] =
                make_uint4(cvt_tf32(vb0.x), cvt_tf32(vb0.y), cvt_tf32(vb0.z), cvt_tf32(vb0.w));
            *(uint4*)&Bs[1 - p][bk + 8][bn4] =
                make_uint4(cvt_tf32(vb1.x), cvt_tf32(vb1.y), cvt_tf32(vb1.z), cvt_tf32(vb1.w));
        }
        p ^= 1;
    }

    // fold bias into the Y half (cols < 256)
    if (rb == 0) {
        #pragma unroll
        for (int nt = 0; nt < 4; nt++) {
            float2 bb = *(const float2*)(b_edge + n0 + wn * 32 + nt * 8 + 2 * t);
            #pragma unroll
            for (int mt = 0; mt < 2; mt++) {
                acc[mt][nt][0] += bb.x; acc[mt][nt][1] += bb.y;
                acc[mt][nt][2] += bb.x; acc[mt][nt][3] += bb.y;
            }
        }
    }

    // epilogue: pack f32 pairs -> bf16x2 words
    #pragma unroll
    for (int mt = 0; mt < 2; mt++) {
        int mrow = m0 + wm * 32 + mt * 16 + g;
        #pragma unroll
        for (int nt = 0; nt < 4; nt++) {
            int colw = (n0 + wn * 32 + nt * 8 + 2 * t) >> 1;
            if (mrow < NN)
                g_YZ[(size_t)mrow * 256 + colw] = f2bf2(acc[mt][nt][0], acc[mt][nt][1]);
            if (mrow + 8 < NN)
                g_YZ[(size_t)(mrow + 8) * 256 + colw] = f2bf2(acc[mt][nt][2], acc[mt][nt][3]);
        }
    }
}

__global__ void zero_s() { g_S[threadIdx.x] = 0.f; }

// ---------------------------------------------------------------------------
// Kernel 3 (v7): edge stage; gathers software-pipelined one sub ahead,
// base combined in bf16x2 (HADD2) then expanded once. Bias pre-folded in Y.
// ---------------------------------------------------------------------------
__global__ __launch_bounds__(256, 2) void edge_kernel(const void* __restrict__ eraw,
                                                      const float* __restrict__ attrs,
                                                      const float* __restrict__ We,
                                                      const float* __restrict__ b_edge) {
    __shared__ __align__(16) u32 attr_s[2][NB][CHUNK][20];
    __shared__ int idx_s[2][128];      // [0..63]=src, [64..127]=dst
    __shared__ float Ssh[NB * HID];

    const int tid = threadIdx.x;
    for (int i = tid; i < NB * HID; i += 256) Ssh[i] = 0.f;

    const int warp = tid >> 5, lane = tid & 31, g = lane >> 2, t = lane & 3;
    const int hbase = warp * 32;

    u32 Bf[4][2][2];
    const int colB = hbase + 8 * (g >> 1) + (g & 1);
    #pragma unroll
    for (int nt = 0; nt < 4; nt++)
        #pragma unroll
        for (int ks = 0; ks < 2; ks++) {
            Bf[nt][ks][0] = cvt_tf32(We[(512 + t + 8 * ks) * 256 + colB + 2 * nt]);
            Bf[nt][ks][1] = cvt_tf32(We[(512 + t + 4 + 8 * ks) * 256 + colB + 2 * nt]);
        }

    const int is64 = g_is_i64;
    const long long* e64 = (const long long*)eraw;
    const int*       e32 = (const int*)eraw;

    const char* yzb = (const char*)g_YZ;
    const u32 co = (u32)(hbase + 8 * t) * 2u;   // byte offset of thread's 16B bf16 slice

    const int sb = tid >> 6, eL = tid & 63;

    u64 acc[NB][4] = {};

    const int nchunks = NE / CHUNK;
    const int stride = gridDim.x;
    int c = blockIdx.x;
    int p = 0;

    {
        const int e0 = c * CHUNK;
        if (tid < 128) {
            size_t gi = (size_t)(tid >> 6) * NE + e0 + (tid & 63);
            if (is64) idx_s[0][tid] = (int)e64[gi];
            else {
                u32 d = smem_u32(&idx_s[0][tid]);
                asm volatile("cp.async.ca.shared.global [%0], [%1], 4;" :: "r"(d), "l"(e32 + gi));
            }
        }
        const float* src = attrs + ((size_t)sb * NE + e0 + eL) * 16;
        u32 d = smem_u32(&attr_s[0][sb][eL][0]);
        #pragma unroll
        for (int j = 0; j < 4; j++)
            asm volatile("cp.async.cg.shared.global [%0], [%1], 16;" :: "r"(d + j * 16), "l"(src + j * 4));
        asm volatile("cp.async.commit_group;");
    }

    for (; c < nchunks; c += stride) {
        const int cn = c + stride;
        if (cn < nchunks) {
            const int e0n = cn * CHUNK;
            if (tid < 128) {
                size_t gi = (size_t)(tid >> 6) * NE + e0n + (tid & 63);
                if (is64) idx_s[1 - p][tid] = (int)e64[gi];
                else {
                    u32 d = smem_u32(&idx_s[1 - p][tid]);
                    asm volatile("cp.async.ca.shared.global [%0], [%1], 4;" :: "r"(d), "l"(e32 + gi));
                }
            }
            const float* src = attrs + ((size_t)sb * NE + e0n + eL) * 16;
            u32 d = smem_u32(&attr_s[1 - p][sb][eL][0]);
            #pragma unroll
            for (int j = 0; j < 4; j++)
                asm volatile("cp.async.cg.shared.global [%0], [%1], 16;" :: "r"(d + j * 16), "l"(src + j * 4));
            asm volatile("cp.async.commit_group;");
            asm volatile("cp.async.wait_group 1;");
        } else {
            asm volatile("cp.async.wait_group 0;");
        }
        __syncthreads();

        // ---- gather pipeline prologue: sub 0 ----
        uint4 Gyl, Gyh, Gzl, Gzh;
        {
            const int sl = idx_s[p][g],      dl = idx_s[p][64 + g];
            const int sh = idx_s[p][g + 8],  dh = idx_s[p][64 + g + 8];
            Gyl = *(const uint4*)(yzb + ((u32)sl * 1024u + co));
            Gyh = *(const uint4*)(yzb + ((u32)sh * 1024u + co));
            Gzl = *(const uint4*)(yzb + ((u32)dl * 1024u + 512u + co));
            Gzh = *(const uint4*)(yzb + ((u32)dh * 1024u + 512u + co));
        }

        #pragma unroll
        for (int sub = 0; sub < 4; sub++) {
            // combine base in bf16x2 domain (frees G for next sub)
            u32 pbl0 = hadd2bf(Gyl.x, Gzl.x), pbl1 = hadd2bf(Gyl.y, Gzl.y);
            u32 pbl2 = hadd2bf(Gyl.z, Gzl.z), pbl3 = hadd2bf(Gyl.w, Gzl.w);
            u32 pbh0 = hadd2bf(Gyh.x, Gzh.x), pbh1 = hadd2bf(Gyh.y, Gzh.y);
            u32 pbh2 = hadd2bf(Gyh.z, Gzh.z), pbh3 = hadd2bf(Gyh.w, Gzh.w);

            // issue next sub's gathers immediately (covered by mma+epilogue)
            if (sub < 3) {
                const int eb = (sub + 1) * 16;
                const int sl = idx_s[p][eb + g],      dl = idx_s[p][64 + eb + g];
                const int sh = idx_s[p][eb + g + 8],  dh = idx_s[p][64 + eb + g + 8];
                Gyl = *(const uint4*)(yzb + ((u32)sl * 1024u + co));
                Gyh = *(const uint4*)(yzb + ((u32)sh * 1024u + co));
                Gzl = *(const uint4*)(yzb + ((u32)dl * 1024u + 512u + co));
                Gzh = *(const uint4*)(yzb + ((u32)dh * 1024u + 512u + co));
            }

            // expand base to f32x2
            u64 bLo[4], bHi[4];
            bLo[0] = bf2f2(pbl0); bLo[1] = bf2f2(pbl1); bLo[2] = bf2f2(pbl2); bLo[3] = bf2f2(pbl3);
            bHi[0] = bf2f2(pbh0); bHi[1] = bf2f2(pbh1); bHi[2] = bf2f2(pbh2); bHi[3] = bf2f2(pbh3);

            const int eb = sub * 16;
            #pragma unroll
            for (int b = 0; b < NB; b++) {
                const u32* arL = attr_s[p][b][eb + g];
                const u32* arH = attr_s[p][b][eb + g + 8];
                u32 a0 = arL[t],      a1 = arH[t];
                u32 a2 = arL[t + 4],  a3 = arH[t + 4];
                u32 a4 = arL[t + 8],  a5 = arH[t + 8];
                u32 a6 = arL[t + 12], a7 = arH[t + 12];
                #pragma unroll
                for (int nt = 0; nt < 4; nt++) {
                    float c0, c1, c2, c3;
                    upk2(bLo[nt], c0, c1);
                    upk2(bHi[nt], c2, c3);
                    float d0, d1, d2, d3;
                    mma_tf32(d0, d1, d2, d3, a0, a1, a2, a3, Bf[nt][0][0], Bf[nt][0][1], c0, c1, c2, c3);
                    mma_tf32(d0, d1, d2, d3, a4, a5, a6, a7, Bf[nt][1][0], Bf[nt][1][1], d0, d1, d2, d3);
                    acc[b][nt] = add2(acc[b][nt], pk2(fmaxf(d0, 0.f), fmaxf(d1, 0.f)));
                    acc[b][nt] = add2(acc[b][nt], pk2(fmaxf(d2, 0.f), fmaxf(d3, 0.f)));
                }
            }
        }
        __syncthreads();
        p ^= 1;
    }

    #pragma unroll
    for (int b = 0; b < NB; b++)
        #pragma unroll
        for (int nt = 0; nt < 4; nt++) {
            u64 v = acc[b][nt];
            v = add2(v, __shfl_down_sync(0xffffffffu, v, 16));
            v = add2(v, __shfl_down_sync(0xffffffffu, v, 8));
            v = add2(v, __shfl_down_sync(0xffffffffu, v, 4));
            acc[b][nt] = v;
        }
    if (lane < 4) {
        #pragma unroll
        for (int b = 0; b < NB; b++)
            #pragma unroll
            for (int nt = 0; nt < 4; nt++) {
                float lo, hi;
                upk2(acc[b][nt], lo, hi);
                int h = hbase + 8 * lane + 2 * nt;
                atomicAdd(&Ssh[b * 256 + h], lo);
                atomicAdd(&Ssh[b * 256 + h + 1], hi);
            }
    }
    __syncthreads();
    for (int i = tid; i < NB * HID; i += 256) atomicAdd(&g_S[i], Ssh[i]);
}

// ---------------------------------------------------------------------------
// Kernel 4: out = (S/NE) @ W_graph + b_graph
// ---------------------------------------------------------------------------
__global__ void final_kernel(const float* __restrict__ Wg,
                             const float* __restrict__ bg,
                             float* __restrict__ out) {
    const int t = threadIdx.x; // 512 threads
    const int b = t >> 7, o = t & 127;
    const float invE = 1.0f / (float)NE;
    float dot = 0.f;
    #pragma unroll 8
    for (int h = 0; h < 256; h++)
        dot += g_S[b * 256 + h] * Wg[h * 128 + o];
    out[t] = fmaf(dot, invE, bg[o]);
}

extern "C" void kernel_launch(void* const* d_in, const int* in_sizes, int n_in,
                              void* d_out, int out_size) {
    const float* x     = (const float*)d_in[0];
    const void*  eidx  = d_in[1];
    const float* attrs = (const float*)d_in[2];
    const float* We    = (const float*)d_in[3];
    const float* be    = (const float*)d_in[4];
    const float* Wg    = (const float*)d_in[5];
    const float* bg    = (const float*)d_in[6];
    float* out = (float*)d_out;

    detect_dtype<<<1, 32>>>(eidx);
    dim3 gn(4, 313);
    node_gemm<<<gn, 256>>>(x, We, be);
    zero_s<<<1, NB * HID>>>();
    edge_kernel<<<296, 256>>>(eidx, attrs, We, be);
    final_kernel<<<1, 512>>>(Wg, bg, out);
}